// round 10
// baseline (speedup 1.0000x reference)
#include <cuda_runtime.h>
#include <math.h>

// Problem shapes (fixed): x (4,1,512,180) float32 -> out (4,1,512,512) float32
#define NB   4
#define H    512
#define WIN  180
#define L    180
#define W    512

// Padded pair table: index k = (b+1) + PAD, zeros outside valid core.
// Entries pre-rescaled: (P[b] - b*dP, dP) so sample = q.x + iy*q.y (iy global).
#define PAD      112
#define PSTRIDE2 744

__device__ static __align__(16) float2 g_pairs[NB * L * PSTRIDE2];

// Per-(tile, angle) metadata: (ca, -sa, as_float(ws), as_float(cnt16))
#define TJ   32
#define TI   32
#define NTX  (W / TJ)      // 16
#define NTY  (W / TI)      // 16
#define NMETA (NTX * NTY * L)
__device__ static float4 g_tmeta[NMETA];

// ---------------------------------------------------------------------------
// Fused prep + meta. Blocks [0, NB*L): blend sinogram columns -> pair table
// (512 threads, one row each, no loop). Blocks [NB*L, ...): tile/angle meta.
// ---------------------------------------------------------------------------
#define PREP_BLOCKS (NB * L)
#define META_BLOCKS ((NMETA + 511) / 512)

__global__ void __launch_bounds__(512) irad_prep_meta(const float* __restrict__ x) {
    __shared__ float col[H];
    const int bx  = blockIdx.x;
    const int tid = threadIdx.x;

    if (bx < PREP_BLOCKS) {
        const int l = bx % L;
        const int n = bx / L;

        float Xc  = fmaf((float)l, 2.0f / 179.0f, -1.0f);
        float ix  = (Xc + 1.0f) * 0.5f * 179.0f;
        float i0f = floorf(ix);
        float wx1 = ix - i0f;
        float wx0 = 1.0f - wx1;
        int   i0  = (int)i0f;
        int   i1  = i0 + 1;
        bool  v0  = (i0 >= 0) && (i0 <= WIN - 1);
        bool  v1  = (i1 >= 0) && (i1 <= WIN - 1);

        const float* xn = x + (size_t)n * H * WIN;
        {
            const int r = tid;                       // 512 threads = H rows
            float a = v0 ? xn[r * WIN + i0] : 0.0f;
            float b = v1 ? xn[r * WIN + i1] : 0.0f;
            col[r] = wx0 * a + wx1 * b;
        }
        __syncthreads();

        float2* pr = g_pairs + (size_t)(n * L + l) * PSTRIDE2;
        for (int k = tid; k < PSTRIDE2; k += 512) {
            int kk = k - PAD;                                    // = b+1
            float P  = (kk >= 1 && kk <= 512) ? col[kk - 1] : 0.0f;
            float Pn = (kk >= 0 && kk <= 511) ? col[kk]     : 0.0f;
            float d  = Pn - P;
            // global rescale: value(iy) = q.x + iy*q.y for floor(iy) = kk-1
            pr[k] = make_float2(fmaf(-(float)(kk - 1), d, P), d);
        }
    } else {
        int idx = (bx - PREP_BLOCKS) * 512 + tid;
        if (idx >= NMETA) return;
        int l    = idx % L;
        int tile = idx / L;
        int j0   = (tile % NTX) * TJ;
        int i0t  = (tile / NTX) * TI;

        float rad = (float)l * (3.14159265358979323846f / 180.0f);
        float ca  = cosf(rad) * 255.5f;
        float sa  = sinf(rad) * 255.5f;

        float uj0 = fmaf((float)j0,           2.0f / 511.0f, -1.0f);
        float uj1 = fmaf((float)(j0 + TJ-1),  2.0f / 511.0f, -1.0f);
        float vi0 = fmaf((float)i0t,          2.0f / 511.0f, -1.0f);
        float vi1 = fmaf((float)(i0t + TI-1), 2.0f / 511.0f, -1.0f);

        float jlo = fminf(ca * uj0, ca * uj1);
        float jhi = fmaxf(ca * uj0, ca * uj1);
        float ilo = fminf(sa * vi0, sa * vi1);
        float ihi = fmaxf(sa * vi0, sa * vi1);
        float iymin = 255.5f + jlo - ihi;
        float iymax = 255.5f + jhi - ilo;

        int ws  = (int)floorf(iymin);
        ws &= ~1;                                   // even for 16B alignment
        int cnt = (int)floorf(iymax) + 3 - ws;      // <= 48 entries
        int cnt16 = (cnt + 1) >> 1;                 // <= 24 16B chunks

        g_tmeta[idx] = make_float4(ca, -sa,
                                   __int_as_float(ws), __int_as_float(cnt16));
    }
}

// ---------------------------------------------------------------------------
// Main: 32x32 tile, 256 threads, 4 px/thread. Double-buffered chunks staged
// with single predicated 16B cp.async per lane using precomputed meta.
// Dual accumulators per pixel halve the serial accumulation chain.
// ---------------------------------------------------------------------------
#define CH   36     // angles per chunk (180 = 5*36)
#define NCH  (L / CH)
#define WMAX 48     // entries per angle window (384 B, 16B-aligned)

__device__ __forceinline__ void cp_async16(unsigned dst, const void* src) {
    asm volatile("cp.async.cg.shared.global [%0], [%1], 16;\n"
                 :: "r"(dst), "l"(src));
}
__device__ __forceinline__ void cp_async_commit() {
    asm volatile("cp.async.commit_group;\n");
}
__device__ __forceinline__ void cp_async_wait_all() {
    asm volatile("cp.async.wait_group 0;\n");
}

__global__ void __launch_bounds__(256) irad_main(float* __restrict__ out) {
    __shared__ float2 sP[2 * CH * WMAX];
    __shared__ float4 sMeta[2 * CH];   // (ca, -sa, as_float(byte base), 0)

    const int n    = blockIdx.z;
    const int j0   = blockIdx.x * TJ;
    const int i0t  = blockIdx.y * TI;
    const int t    = threadIdx.x;
    const int lane = t & 31;
    const int wid  = t >> 5;           // 0..7
    const int j    = j0 + lane;

    const float uj = fmaf((float)j, 2.0f / 511.0f, -1.0f);

    float ui[4], accX[4], accY[4];
#pragma unroll
    for (int k = 0; k < 4; k++) {
        ui[k]   = fmaf((float)(i0t + wid + 8 * k), 2.0f / 511.0f, -1.0f);
        accX[k] = 0.0f;
        accY[k] = 0.0f;
    }

    const float2* gp = g_pairs + (size_t)n * L * PSTRIDE2;
    const float4* tm = g_tmeta + (size_t)(blockIdx.y * NTX + blockIdx.x) * L;
    const char* sPc = (const char*)sP;
    const unsigned sPb = (unsigned)__cvta_generic_to_shared(sP);

    // ---- stage(chunk c into buffer b): LDG.128 meta + 1 cp.async/lane ----
    auto stage = [&](int c, int b) {
        const int c0 = c * CH;
        const int bofs = b * CH;
        for (int lc = wid; lc < CH; lc += 8) {
            const float4 m = tm[c0 + lc];
            const int ws    = __float_as_int(m.z);
            const int cnt16 = __float_as_int(m.w);

            const float2* src = gp + (size_t)(c0 + lc) * PSTRIDE2 + (ws + PAD);
            unsigned dst = sPb + (unsigned)((bofs + lc) * WMAX) * 8u;
            if (lane < cnt16)
                cp_async16(dst + (unsigned)lane * 16u, src + 2 * lane);
            if (lane == 0) {
                int ab8 = (((bofs + lc) * WMAX) + 1 - ws) * 8;
                sMeta[bofs + lc] = make_float4(m.x, m.y, __int_as_float(ab8), 0.0f);
            }
        }
        cp_async_commit();
    };

    stage(0, 0);

    for (int c = 0; c < NCH; c++) {
        const int b = c & 1;
        cp_async_wait_all();
        __syncthreads();                       // buf b ready; buf b^1 free

        if (c + 1 < NCH) stage(c + 1, b ^ 1);  // issue-only prefetch

        const float4* mp = sMeta + b * CH;
        for (int lc = 0; lc < CH; lc++) {
            const float4 m  = mp[lc];
            const char* pb  = sPc + __float_as_int(m.z);
            const float t0  = fmaf(m.x, uj, 255.5f);
#pragma unroll
            for (int k = 0; k < 4; k++) {
                float iy = fmaf(m.y, ui[k], t0);
                int   e  = __float2int_rd(iy);
                float2 q = *(const float2*)(pb + ((unsigned)e << 3));
                accX[k] += q.x;
                accY[k] = fmaf(iy, q.y, accY[k]);
            }
        }
    }

    const float scale = (float)(M_PI / 360.0);   // pi / (2*L)
    float* po = out + ((size_t)(n * W + i0t + wid) * W) + j;
#pragma unroll
    for (int k = 0; k < 4; k++) {
        po[(size_t)(8 * k) * W] = (accX[k] + accY[k]) * scale;
    }
}

// ---------------------------------------------------------------------------
extern "C" void kernel_launch(void* const* d_in, const int* in_sizes, int n_in,
                              void* d_out, int out_size) {
    const float* x = (const float*)d_in[0];
    float* out = (float*)d_out;
    (void)in_sizes; (void)n_in; (void)out_size;

    irad_prep_meta<<<PREP_BLOCKS + META_BLOCKS, 512>>>(x);
    irad_main<<<dim3(NTX, NTY, NB), 256>>>(out);
}

// round 11
// speedup vs baseline: 1.0258x; 1.0258x over previous
#include <cuda_runtime.h>
#include <math.h>

// Problem shapes (fixed): x (4,1,512,180) float32 -> out (4,1,512,512) float32
#define NB   4
#define H    512
#define WIN  180
#define L    180
#define W    512

// Padded pair table: index k = (b+1) + PAD, zeros outside valid core.
// Entries pre-rescaled: (P[b] - b*dP, dP) so sample = q.x + iy*q.y (iy global).
#define PAD      112
#define PSTRIDE2 744

__device__ static __align__(16) float2 g_pairs[NB * L * PSTRIDE2];

// Per-(tile, angle) metadata: (ca, -sa, as_float(ws), as_float(cnt16))
#define TJ   32
#define TI   32
#define NTX  (W / TJ)      // 16
#define NTY  (W / TI)      // 16
#define NMETA (NTX * NTY * L)
__device__ static float4 g_tmeta[NMETA];

// ---------------------------------------------------------------------------
// Fused prep + meta. Blocks [0, NB*L): blend sinogram columns -> pair table
// (512 threads, one row each, no loop). Blocks [NB*L, ...): tile/angle meta.
// ---------------------------------------------------------------------------
#define PREP_BLOCKS (NB * L)
#define META_BLOCKS ((NMETA + 511) / 512)

__global__ void __launch_bounds__(512) irad_prep_meta(const float* __restrict__ x) {
    __shared__ float col[H];
    const int bx  = blockIdx.x;
    const int tid = threadIdx.x;

    if (bx < PREP_BLOCKS) {
        const int l = bx % L;
        const int n = bx / L;

        float Xc  = fmaf((float)l, 2.0f / 179.0f, -1.0f);
        float ix  = (Xc + 1.0f) * 0.5f * 179.0f;
        float i0f = floorf(ix);
        float wx1 = ix - i0f;
        float wx0 = 1.0f - wx1;
        int   i0  = (int)i0f;
        int   i1  = i0 + 1;
        bool  v0  = (i0 >= 0) && (i0 <= WIN - 1);
        bool  v1  = (i1 >= 0) && (i1 <= WIN - 1);

        const float* xn = x + (size_t)n * H * WIN;
        {
            const int r = tid;                       // 512 threads = H rows
            float a = v0 ? xn[r * WIN + i0] : 0.0f;
            float b = v1 ? xn[r * WIN + i1] : 0.0f;
            col[r] = wx0 * a + wx1 * b;
        }
        __syncthreads();

        float2* pr = g_pairs + (size_t)(n * L + l) * PSTRIDE2;
        for (int k = tid; k < PSTRIDE2; k += 512) {
            int kk = k - PAD;                                    // = b+1
            float P  = (kk >= 1 && kk <= 512) ? col[kk - 1] : 0.0f;
            float Pn = (kk >= 0 && kk <= 511) ? col[kk]     : 0.0f;
            float d  = Pn - P;
            // global rescale: value(iy) = q.x + iy*q.y for floor(iy) = kk-1
            pr[k] = make_float2(fmaf(-(float)(kk - 1), d, P), d);
        }
    } else {
        int idx = (bx - PREP_BLOCKS) * 512 + tid;
        if (idx >= NMETA) return;
        int l    = idx % L;
        int tile = idx / L;
        int j0   = (tile % NTX) * TJ;
        int i0t  = (tile / NTX) * TI;

        float rad = (float)l * (3.14159265358979323846f / 180.0f);
        float ca  = cosf(rad) * 255.5f;
        float sa  = sinf(rad) * 255.5f;

        float uj0 = fmaf((float)j0,           2.0f / 511.0f, -1.0f);
        float uj1 = fmaf((float)(j0 + TJ-1),  2.0f / 511.0f, -1.0f);
        float vi0 = fmaf((float)i0t,          2.0f / 511.0f, -1.0f);
        float vi1 = fmaf((float)(i0t + TI-1), 2.0f / 511.0f, -1.0f);

        float jlo = fminf(ca * uj0, ca * uj1);
        float jhi = fmaxf(ca * uj0, ca * uj1);
        float ilo = fminf(sa * vi0, sa * vi1);
        float ihi = fmaxf(sa * vi0, sa * vi1);
        float iymin = 255.5f + jlo - ihi;
        float iymax = 255.5f + jhi - ilo;

        int ws  = (int)floorf(iymin);
        ws &= ~1;                                   // even for 16B alignment
        int cnt = (int)floorf(iymax) + 3 - ws;      // <= 48 entries
        int cnt16 = (cnt + 1) >> 1;                 // <= 24 16B chunks

        g_tmeta[idx] = make_float4(ca, -sa,
                                   __int_as_float(ws), __int_as_float(cnt16));
    }
}

// ---------------------------------------------------------------------------
// Main: 32x32 tile, 256 threads, 4 px/thread. Double-buffered chunks staged
// with single predicated 16B cp.async per lane using precomputed meta.
// Single interleaved accumulator (precision + regs).
// ---------------------------------------------------------------------------
#define CH   36     // angles per chunk (180 = 5*36)
#define NCH  (L / CH)
#define WMAX 48     // entries per angle window (384 B, 16B-aligned)

__device__ __forceinline__ void cp_async16(unsigned dst, const void* src) {
    asm volatile("cp.async.cg.shared.global [%0], [%1], 16;\n"
                 :: "r"(dst), "l"(src));
}
__device__ __forceinline__ void cp_async_commit() {
    asm volatile("cp.async.commit_group;\n");
}
__device__ __forceinline__ void cp_async_wait_all() {
    asm volatile("cp.async.wait_group 0;\n");
}

__global__ void __launch_bounds__(256) irad_main(float* __restrict__ out) {
    __shared__ float2 sP[2 * CH * WMAX];
    __shared__ float4 sMeta[2 * CH];   // (ca, -sa, as_float(byte base), 0)

    const int n    = blockIdx.z;
    const int j0   = blockIdx.x * TJ;
    const int i0t  = blockIdx.y * TI;
    const int t    = threadIdx.x;
    const int lane = t & 31;
    const int wid  = t >> 5;           // 0..7
    const int j    = j0 + lane;

    const float uj = fmaf((float)j, 2.0f / 511.0f, -1.0f);

    float ui[4], acc[4];
#pragma unroll
    for (int k = 0; k < 4; k++) {
        ui[k]  = fmaf((float)(i0t + wid + 8 * k), 2.0f / 511.0f, -1.0f);
        acc[k] = 0.0f;
    }

    const float2* gp = g_pairs + (size_t)n * L * PSTRIDE2;
    const float4* tm = g_tmeta + (size_t)(blockIdx.y * NTX + blockIdx.x) * L;
    const char* sPc = (const char*)sP;
    const unsigned sPb = (unsigned)__cvta_generic_to_shared(sP);

    // ---- stage(chunk c into buffer b): LDG.128 meta + 1 cp.async/lane ----
    auto stage = [&](int c, int b) {
        const int c0 = c * CH;
        const int bofs = b * CH;
        for (int lc = wid; lc < CH; lc += 8) {
            const float4 m = tm[c0 + lc];
            const int ws    = __float_as_int(m.z);
            const int cnt16 = __float_as_int(m.w);

            const float2* src = gp + (size_t)(c0 + lc) * PSTRIDE2 + (ws + PAD);
            unsigned dst = sPb + (unsigned)((bofs + lc) * WMAX) * 8u;
            if (lane < cnt16)
                cp_async16(dst + (unsigned)lane * 16u, src + 2 * lane);
            if (lane == 0) {
                int ab8 = (((bofs + lc) * WMAX) + 1 - ws) * 8;
                sMeta[bofs + lc] = make_float4(m.x, m.y, __int_as_float(ab8), 0.0f);
            }
        }
        cp_async_commit();
    };

    stage(0, 0);

    for (int c = 0; c < NCH; c++) {
        const int b = c & 1;
        cp_async_wait_all();
        __syncthreads();                       // buf b ready; buf b^1 free

        if (c + 1 < NCH) stage(c + 1, b ^ 1);  // issue-only prefetch

        const float4* mp = sMeta + b * CH;
        for (int lc = 0; lc < CH; lc++) {
            const float4 m  = mp[lc];
            const char* pb  = sPc + __float_as_int(m.z);
            const float t0  = fmaf(m.x, uj, 255.5f);
#pragma unroll
            for (int k = 0; k < 4; k++) {
                float iy = fmaf(m.y, ui[k], t0);
                int   e  = __float2int_rd(iy);
                float2 q = *(const float2*)(pb + ((unsigned)e << 3));
                acc[k] = fmaf(iy, q.y, acc[k] + q.x);
            }
        }
    }

    const float scale = (float)(M_PI / 360.0);   // pi / (2*L)
    float* po = out + ((size_t)(n * W + i0t + wid) * W) + j;
#pragma unroll
    for (int k = 0; k < 4; k++) {
        po[(size_t)(8 * k) * W] = acc[k] * scale;
    }
}

// ---------------------------------------------------------------------------
extern "C" void kernel_launch(void* const* d_in, const int* in_sizes, int n_in,
                              void* d_out, int out_size) {
    const float* x = (const float*)d_in[0];
    float* out = (float*)d_out;
    (void)in_sizes; (void)n_in; (void)out_size;

    irad_prep_meta<<<PREP_BLOCKS + META_BLOCKS, 512>>>(x);
    irad_main<<<dim3(NTX, NTY, NB), 256>>>(out);
}